// round 11
// baseline (speedup 1.0000x reference)
#include <cuda_runtime.h>
#include <cuda_bf16.h>

// LSTM_20452634263894: B=32768, T=512, I=2, H=16.
// R0 skeleton (1 thread per batch row, proven) + R4-validated upgrades:
//  - i/f/o weight rows & bias pre-scaled by 0.5 (sigmoid via tanh, fold 0.5x)
//  - packed f32x2 activation on R0's native acc layout
//  - float4 x prefetch (2 timesteps per load)
// All local arrays constant-indexed (register-promotable).

#define B_TOT 32768
#define T_LEN 512
#define I_DIM 2
#define H_DIM 16
#define G_DIM 64   // 4*H
#define NP    32   // gate pairs: p=0..7 i, 8..15 f, 16..23 g, 24..31 o

typedef unsigned long long u64;

__device__ __forceinline__ u64 pack2(float lo, float hi) {
    u64 r;
    asm("mov.b64 %0, {%1, %2};" : "=l"(r) : "f"(lo), "f"(hi));
    return r;
}
__device__ __forceinline__ void unpack2(u64 v, float& lo, float& hi) {
    asm("mov.b64 {%0, %1}, %2;" : "=f"(lo), "=f"(hi) : "l"(v));
}
__device__ __forceinline__ u64 ffma2(u64 a, u64 b, u64 c) {
    u64 d;
    asm("fma.rn.f32x2 %0, %1, %2, %3;" : "=l"(d) : "l"(a), "l"(b), "l"(c));
    return d;
}
__device__ __forceinline__ u64 mul2(u64 a, u64 b) {
    u64 d;
    asm("mul.rn.f32x2 %0, %1, %2;" : "=l"(d) : "l"(a), "l"(b));
    return d;
}
__device__ __forceinline__ float tanh_fast(float x) {
    float y;
    asm("tanh.approx.f32 %0, %1;" : "=f"(y) : "f"(x));
    return y;
}

// Gate-pair p -> 0.5 prescale for i/f/o rows (p<16 or p>=24), 1.0 for g.
__device__ __forceinline__ float pscale(int p) {
    return (p >= 16 && p < 24) ? 1.0f : 0.5f;
}

__global__ void __launch_bounds__(128, 2) lstm_fused_kernel(
    const float* __restrict__ x,
    const float* __restrict__ W_ih, const float* __restrict__ W_hh,
    const float* __restrict__ b_ih, const float* __restrict__ b_hh,
    const float* __restrict__ W1,  const float* __restrict__ b1,
    const float* __restrict__ W2,  const float* __restrict__ b2,
    float* __restrict__ out)
{
    // Packed weights in shared. sWhh[k][p] = (W_hh[2p][k], W_hh[2p+1][k]) * s.
    __shared__ __align__(16) u64 sWhh[H_DIM][NP];
    __shared__ __align__(16) u64 sWih[2][NP];
    __shared__ __align__(16) u64 sBias[NP];
    __shared__ float sW1[H_DIM * H_DIM];
    __shared__ float sb1[H_DIM];
    __shared__ float sW2[I_DIM * H_DIM];
    __shared__ float sb2[I_DIM];

    const int tid = threadIdx.x;

    for (int idx = tid; idx < H_DIM * NP; idx += blockDim.x) {
        int k = idx / NP, p = idx % NP;
        float sc = pscale(p);
        sWhh[k][p] = pack2(W_hh[(2 * p) * H_DIM + k] * sc,
                           W_hh[(2 * p + 1) * H_DIM + k] * sc);
    }
    for (int idx = tid; idx < 2 * NP; idx += blockDim.x) {
        int cc = idx / NP, p = idx % NP;
        float sc = pscale(p);
        sWih[cc][p] = pack2(W_ih[(2 * p) * I_DIM + cc] * sc,
                            W_ih[(2 * p + 1) * I_DIM + cc] * sc);
    }
    for (int p = tid; p < NP; p += blockDim.x) {
        float sc = pscale(p);
        sBias[p] = pack2((b_ih[2 * p] + b_hh[2 * p]) * sc,
                         (b_ih[2 * p + 1] + b_hh[2 * p + 1]) * sc);
    }
    for (int idx = tid; idx < H_DIM * H_DIM; idx += blockDim.x) sW1[idx] = W1[idx];
    for (int idx = tid; idx < H_DIM; idx += blockDim.x) sb1[idx] = b1[idx];
    for (int idx = tid; idx < I_DIM * H_DIM; idx += blockDim.x) sW2[idx] = W2[idx];
    for (int idx = tid; idx < I_DIM; idx += blockDim.x) sb2[idx] = b2[idx];
    __syncthreads();

    const int b = blockIdx.x * blockDim.x + tid;
    const float4* __restrict__ xrow =
        reinterpret_cast<const float4*>(x + (size_t)b * (T_LEN * I_DIM));

    float h[H_DIM];
    u64   c2[8];                 // packed cell state: c2[j] = (c[2j], c[2j+1])
#pragma unroll
    for (int u = 0; u < H_DIM; ++u) h[u] = 0.0f;
#pragma unroll
    for (int j = 0; j < 8; ++j) c2[j] = 0ull;

    // Combined, pre-scaled bias in registers (removes per-step bias LDS).
    u64 biasr[NP];
#pragma unroll
    for (int p = 0; p < NP; ++p) biasr[p] = sBias[p];

    const u64 H05 = pack2(0.5f, 0.5f);

    const ulonglong2* __restrict__ wih0 =
        reinterpret_cast<const ulonglong2*>(&sWih[0][0]);
    const ulonglong2* __restrict__ wih1 =
        reinterpret_cast<const ulonglong2*>(&sWih[1][0]);

    float4 xb = __ldg(xrow);                       // steps 0,1

#pragma unroll 1
    for (int t2 = 0; t2 < T_LEN / 2; ++t2) {
        float4 xn;
        if (t2 + 1 < T_LEN / 2) xn = __ldg(xrow + t2 + 1);

#pragma unroll
        for (int sub = 0; sub < 2; ++sub) {
            const float x0 = sub ? xb.z : xb.x;
            const float x1 = sub ? xb.w : xb.y;
            const u64 px0 = pack2(x0, x0);
            const u64 px1 = pack2(x1, x1);

            u64 acc[NP];
            // acc = bias + x0*Wih[:,0] + x1*Wih[:,1]
#pragma unroll
            for (int p2 = 0; p2 < NP / 2; ++p2) {
                ulonglong2 w0 = wih0[p2];
                ulonglong2 w1 = wih1[p2];
                acc[2 * p2]     = ffma2(px1, w1.x, ffma2(px0, w0.x, biasr[2 * p2]));
                acc[2 * p2 + 1] = ffma2(px1, w1.y, ffma2(px0, w0.y, biasr[2 * p2 + 1]));
            }
            // Recurrent matvec: acc[p] += h[k] * Whh_pair[k][p]
#pragma unroll
            for (int k = 0; k < H_DIM; ++k) {
                u64 hk = pack2(h[k], h[k]);
                const ulonglong2* __restrict__ row =
                    reinterpret_cast<const ulonglong2*>(&sWhh[k][0]);
#pragma unroll
                for (int p2 = 0; p2 < NP / 2; ++p2) {
                    ulonglong2 w = row[p2];
                    acc[2 * p2]     = ffma2(hk, w.x, acc[2 * p2]);
                    acc[2 * p2 + 1] = ffma2(hk, w.y, acc[2 * p2 + 1]);
                }
            }
            // Packed activation. acc[j]=i, acc[8+j]=f, acc[16+j]=g, acc[24+j]=o
            // for unit pair (2j, 2j+1); i/f/o pre-scaled by 0.5.
#pragma unroll
            for (int j = 0; j < 8; ++j) {
                float u, v;
                unpack2(acc[j], u, v);
                u64 i2 = ffma2(H05, pack2(tanh_fast(u), tanh_fast(v)), H05);
                unpack2(acc[8 + j], u, v);
                u64 f2 = ffma2(H05, pack2(tanh_fast(u), tanh_fast(v)), H05);
                unpack2(acc[16 + j], u, v);
                u64 g2 = pack2(tanh_fast(u), tanh_fast(v));
                unpack2(acc[24 + j], u, v);
                u64 o2 = ffma2(H05, pack2(tanh_fast(u), tanh_fast(v)), H05);
                u64 cn = ffma2(f2, c2[j], mul2(i2, g2));
                c2[j] = cn;
                unpack2(cn, u, v);
                u64 hv = mul2(o2, pack2(tanh_fast(u), tanh_fast(v)));
                unpack2(hv, h[2 * j], h[2 * j + 1]);   // constant indices
            }
        } // sub
        xb = xn;   // dead value on final iteration; never read
    }

    // MLP head: y = tanh(h @ W1^T + b1) @ W2^T + b2
    float y0 = sb2[0], y1 = sb2[1];
#pragma unroll
    for (int j = 0; j < H_DIM; ++j) {
        float z = sb1[j];
#pragma unroll
        for (int k = 0; k < H_DIM; ++k) z = fmaf(h[k], sW1[j * H_DIM + k], z);
        z = tanh_fast(z);
        y0 = fmaf(z, sW2[0 * H_DIM + j], y0);
        y1 = fmaf(z, sW2[1 * H_DIM + j], y1);
    }
    reinterpret_cast<float2*>(out)[b] = make_float2(y0, y1);
}

extern "C" void kernel_launch(void* const* d_in, const int* in_sizes, int n_in,
                              void* d_out, int out_size) {
    const float* x    = (const float*)d_in[0];
    const float* W_ih = (const float*)d_in[1];
    const float* W_hh = (const float*)d_in[2];
    const float* b_ih = (const float*)d_in[3];
    const float* b_hh = (const float*)d_in[4];
    const float* W1   = (const float*)d_in[5];
    const float* b1   = (const float*)d_in[6];
    const float* W2   = (const float*)d_in[7];
    const float* b2   = (const float*)d_in[8];
    float* out = (float*)d_out;

    dim3 block(128);
    dim3 grid(B_TOT / 128);   // 256 CTAs, one thread per batch row
    lstm_fused_kernel<<<grid, block>>>(x, W_ih, W_hh, b_ih, b_hh,
                                       W1, b1, W2, b2, out);
}

// round 12
// speedup vs baseline: 2.4981x; 2.4981x over previous
#include <cuda_runtime.h>
#include <cuda_bf16.h>

// LSTM_20452634263894: B=32768, T=512, I=2, H=16.
// R6's numerically-proven pair-split kernel (passed, rel 2.86e-6) with ALL
// local-memory demotion sources removed:
//  - no pointer selection of local arrays (statically-bound refs only)
//  - no runtime-variable indices into local arrays (parity handled by FSEL
//    with constant indices; dynamic indexing only on SHARED addresses)
// Scheme: thread pair (even,odd lane) covers batch rows (2p, 2p+1); even
// lane owns units 0-7, odd lane units 8-15, for BOTH rows. Each weight
// LDS.128 feeds 4 ffma2. h exchanged via shfl.bfly(1) + select.
// i/f/o weight rows pre-scaled by 0.5 (sigmoid = 0.5*tanh(x_pre)+0.5).

#define B_TOT  32768
#define T_LEN  512
#define H_DIM  16
#define NTHR   128
#define NCTA   256   // 32768 threads; pair of threads per 2 rows

typedef unsigned long long u64;

__device__ __forceinline__ u64 pack2(float lo, float hi) {
    u64 r;
    asm("mov.b64 %0, {%1, %2};" : "=l"(r) : "f"(lo), "f"(hi));
    return r;
}
__device__ __forceinline__ void unpack2(u64 v, float& lo, float& hi) {
    asm("mov.b64 {%0, %1}, %2;" : "=f"(lo), "=f"(hi) : "l"(v));
}
__device__ __forceinline__ u64 ffma2(u64 a, u64 b, u64 c) {
    u64 d;
    asm("fma.rn.f32x2 %0, %1, %2, %3;" : "=l"(d) : "l"(a), "l"(b), "l"(c));
    return d;
}
__device__ __forceinline__ u64 mul2(u64 a, u64 b) {
    u64 d;
    asm("mul.rn.f32x2 %0, %1, %2;" : "=l"(d) : "l"(a), "l"(b));
    return d;
}
__device__ __forceinline__ float tanh_fast(float x) {
    float y;
    asm("tanh.approx.f32 %0, %1;" : "=f"(y) : "f"(x));
    return y;
}

// Smem u64 entry e (0..31) -> gate-pair p. (Verbatim from the R6 pass.)
// Thread parity par reads ulonglong2 indices (2j+par), j=0..7, i.e. u64
// entries e=4j+2par, 4j+2par+1 -> slots s=2j,2j+1 of that thread, covering
// own-local unit pair (2*(s&3), +1) of gate type (s>>2), own units par*8..+7.
__device__ __forceinline__ void decode_entry(int e, int& p, float& sc) {
    int j2 = e >> 2, par = (e >> 1) & 1, lane = e & 1;
    int s = 2 * j2 + lane;           // slot within owning thread (0..15)
    int grp = s >> 2, jj = s & 3;    // 0=i,1=f,2=g,3=o
    p = grp * 8 + par * 4 + jj;
    sc = (grp == 2) ? 1.0f : 0.5f;
}

// Activation + exchange for ONE row. All arrays statically bound refs;
// h written with CONSTANT indices via parity-select. Slots: a[0..3]=i,
// a[4..7]=f, a[8..11]=g, a[12..15]=o (i/f/o pre-scaled by 0.5).
__device__ __forceinline__ void act_row(u64 (&a)[16], u64 (&cc)[4],
                                        float (&h)[16], int parity, u64 H05) {
#pragma unroll
    for (int j = 0; j < 4; ++j) {
        float u, v;
        unpack2(a[j], u, v);
        u64 i2 = ffma2(H05, pack2(tanh_fast(u), tanh_fast(v)), H05);
        unpack2(a[4 + j], u, v);
        u64 f2 = ffma2(H05, pack2(tanh_fast(u), tanh_fast(v)), H05);
        unpack2(a[8 + j], u, v);
        u64 g2 = pack2(tanh_fast(u), tanh_fast(v));
        unpack2(a[12 + j], u, v);
        u64 o2 = ffma2(H05, pack2(tanh_fast(u), tanh_fast(v)), H05);
        u64 cn = ffma2(f2, cc[j], mul2(i2, g2));
        cc[j] = cn;
        unpack2(cn, u, v);
        u64 hv = mul2(o2, pack2(tanh_fast(u), tanh_fast(v)));
        float hlo, hhi;
        unpack2(hv, hlo, hhi);
        // Uniform shfl (no divergence), then constant-index selects.
        float olo = __shfl_xor_sync(0xffffffffu, hlo, 1);
        float ohi = __shfl_xor_sync(0xffffffffu, hhi, 1);
        // parity 0 owns global units 2j,2j+1 ; parity 1 owns 8+2j,8+2j+1.
        h[2 * j]         = (parity == 0) ? hlo : olo;
        h[2 * j + 1]     = (parity == 0) ? hhi : ohi;
        h[8 + 2 * j]     = (parity == 0) ? olo : hlo;
        h[8 + 2 * j + 1] = (parity == 0) ? ohi : hhi;
    }
}

__global__ void __launch_bounds__(NTHR) lstm_split2_kernel(
    const float* __restrict__ x,
    const float* __restrict__ W_ih, const float* __restrict__ W_hh,
    const float* __restrict__ b_ih, const float* __restrict__ b_hh,
    const float* __restrict__ W1,  const float* __restrict__ b1,
    const float* __restrict__ W2,  const float* __restrict__ b2,
    float* __restrict__ out)
{
    __shared__ __align__(16) u64 sWhh[H_DIM][32];
    __shared__ __align__(16) u64 sWih[2][32];
    __shared__ __align__(16) u64 sBias[32];
    __shared__ float sW1[H_DIM * H_DIM];
    __shared__ float sb1[H_DIM];
    __shared__ float sW2[2 * H_DIM];
    __shared__ float sb2[2];

    const int tid = threadIdx.x;

    for (int idx = tid; idx < H_DIM * 32; idx += NTHR) {
        int k = idx >> 5, e = idx & 31;
        int p; float sc; decode_entry(e, p, sc);
        sWhh[k][e] = pack2(W_hh[(2 * p) * H_DIM + k] * sc,
                           W_hh[(2 * p + 1) * H_DIM + k] * sc);
    }
    for (int idx = tid; idx < 2 * 32; idx += NTHR) {
        int cc = idx >> 5, e = idx & 31;
        int p; float sc; decode_entry(e, p, sc);
        sWih[cc][e] = pack2(W_ih[(2 * p) * 2 + cc] * sc,
                            W_ih[(2 * p + 1) * 2 + cc] * sc);
    }
    for (int e = tid; e < 32; e += NTHR) {
        int p; float sc; decode_entry(e, p, sc);
        sBias[e] = pack2((b_ih[2 * p] + b_hh[2 * p]) * sc,
                         (b_ih[2 * p + 1] + b_hh[2 * p + 1]) * sc);
    }
    for (int idx = tid; idx < H_DIM * H_DIM; idx += NTHR) sW1[idx] = W1[idx];
    for (int idx = tid; idx < H_DIM; idx += NTHR) sb1[idx] = b1[idx];
    for (int idx = tid; idx < 2 * H_DIM; idx += NTHR) sW2[idx] = W2[idx];
    for (int idx = tid; idx < 2; idx += NTHR) sb2[idx] = b2[idx];
    __syncthreads();

    const int gt     = blockIdx.x * NTHR + tid;   // 32768 threads
    const int parity = gt & 1;
    const int rowA   = (gt >> 1) * 2;

    const float4* __restrict__ xpA =
        reinterpret_cast<const float4*>(x + (size_t)rowA * (T_LEN * 2));
    const float4* __restrict__ xpB =
        reinterpret_cast<const float4*>(x + (size_t)(rowA + 1) * (T_LEN * 2));

    float hA[H_DIM], hB[H_DIM];   // full hidden state, both rows (const idx)
    u64   cA[4], cB[4];           // cell state: own 8 units as 4 pairs
#pragma unroll
    for (int u = 0; u < H_DIM; ++u) { hA[u] = 0.0f; hB[u] = 0.0f; }
#pragma unroll
    for (int j = 0; j < 4; ++j) { cA[j] = 0ull; cB[j] = 0ull; }

    const u64 H05 = pack2(0.5f, 0.5f);

    float4 xbA = __ldg(xpA);
    float4 xbB = __ldg(xpB);

#pragma unroll 1
    for (int t2 = 0; t2 < T_LEN / 2; ++t2) {
        const int tn = (t2 + 1 < T_LEN / 2) ? (t2 + 1) : t2;  // clamped
        float4 xnA = __ldg(xpA + tn);
        float4 xnB = __ldg(xpB + tn);

#pragma unroll
        for (int sub = 0; sub < 2; ++sub) {
            const float xA0 = sub ? xbA.z : xbA.x;
            const float xA1 = sub ? xbA.w : xbA.y;
            const float xB0 = sub ? xbB.z : xbB.x;
            const float xB1 = sub ? xbB.w : xbB.y;
            const u64 pA0 = pack2(xA0, xA0), pA1 = pack2(xA1, xA1);
            const u64 pB0 = pack2(xB0, xB0), pB1 = pack2(xB1, xB1);

            u64 aA[16], aB[16];

            const ulonglong2* __restrict__ bp =
                reinterpret_cast<const ulonglong2*>(&sBias[0]);
            const ulonglong2* __restrict__ wp0 =
                reinterpret_cast<const ulonglong2*>(&sWih[0][0]);
            const ulonglong2* __restrict__ wp1 =
                reinterpret_cast<const ulonglong2*>(&sWih[1][0]);
#pragma unroll
            for (int j = 0; j < 8; ++j) {
                const int e = 2 * j + parity;     // shared index: OK dynamic
                ulonglong2 bb = bp[e];
                ulonglong2 w0 = wp0[e];
                ulonglong2 w1 = wp1[e];
                aA[2 * j]     = ffma2(pA1, w1.x, ffma2(pA0, w0.x, bb.x));
                aA[2 * j + 1] = ffma2(pA1, w1.y, ffma2(pA0, w0.y, bb.y));
                aB[2 * j]     = ffma2(pB1, w1.x, ffma2(pB0, w0.x, bb.x));
                aB[2 * j + 1] = ffma2(pB1, w1.y, ffma2(pB0, w0.y, bb.y));
            }

            // Recurrent matvec: constant k into local h, dynamic index only
            // on shared. Each LDS.128 feeds 4 ffma2 (2 rows x 2 slots).
#pragma unroll
            for (int k = 0; k < H_DIM; ++k) {
                const u64 hkA = pack2(hA[k], hA[k]);
                const u64 hkB = pack2(hB[k], hB[k]);
                const ulonglong2* __restrict__ wr =
                    reinterpret_cast<const ulonglong2*>(&sWhh[k][0]);
#pragma unroll
                for (int j = 0; j < 8; ++j) {
                    ulonglong2 w = wr[2 * j + parity];
                    aA[2 * j]     = ffma2(hkA, w.x, aA[2 * j]);
                    aA[2 * j + 1] = ffma2(hkA, w.y, aA[2 * j + 1]);
                    aB[2 * j]     = ffma2(hkB, w.x, aB[2 * j]);
                    aB[2 * j + 1] = ffma2(hkB, w.y, aB[2 * j + 1]);
                }
            }

            // Statically-bound activation + exchange (h dead after matvec).
            act_row(aA, cA, hA, parity, H05);
            act_row(aB, cB, hB, parity, H05);
        } // sub
        xbA = xnA; xbB = xnB;
    }

    // MLP head. Select h into a constant-indexed temp (FSEL, promotable).
    float hsel[H_DIM];
#pragma unroll
    for (int k = 0; k < H_DIM; ++k)
        hsel[k] = (parity == 0) ? hA[k] : hB[k];

    float y0 = sb2[0], y1 = sb2[1];
#pragma unroll
    for (int j = 0; j < H_DIM; ++j) {
        float z = sb1[j];
#pragma unroll
        for (int k = 0; k < H_DIM; ++k)
            z = fmaf(hsel[k], sW1[j * H_DIM + k], z);
        z = tanh_fast(z);
        y0 = fmaf(z, sW2[j], y0);
        y1 = fmaf(z, sW2[H_DIM + j], y1);
    }
    reinterpret_cast<float2*>(out)[rowA + parity] = make_float2(y0, y1);
}

extern "C" void kernel_launch(void* const* d_in, const int* in_sizes, int n_in,
                              void* d_out, int out_size) {
    const float* x    = (const float*)d_in[0];
    const float* W_ih = (const float*)d_in[1];
    const float* W_hh = (const float*)d_in[2];
    const float* b_ih = (const float*)d_in[3];
    const float* b_hh = (const float*)d_in[4];
    const float* W1   = (const float*)d_in[5];
    const float* b1   = (const float*)d_in[6];
    const float* W2   = (const float*)d_in[7];
    const float* b2   = (const float*)d_in[8];
    float* out = (float*)d_out;

    lstm_split2_kernel<<<NCTA, NTHR>>>(x, W_ih, W_hh, b_ih, b_hh,
                                       W1, b1, W2, b2, out);
}